// round 9
// baseline (speedup 1.0000x reference)
#include <cuda_runtime.h>
#include <cuda_fp16.h>
#include <cstdint>

// ============================================================================
// out[8192,4096] = fwht(x) @ W^T + b  ==  x @ fwht(W)^T + b   (H symmetric)
//  K1 (merged): blocks 0..4095    -> Wh = fp16(fwht(W row) / 64)
//               blocks 4096..6143 -> Xh = fp16(x)
//  K2: persistent fp16 HMMA GEMM, 256x128 tile, 4-slot cp.async ring that is
//      CONTINUOUS ACROSS TILES (next tile's stages prefetch during this
//      tile's tail + epilogue), wait_group 2 steady state, fused bias.
// ============================================================================

#define M_TOTAL 8192
#define N_TOTAL 4096
#define K_TOTAL 4096

#define TILE_M 256
#define TILE_N 128
#define KS 64
#define STAGES 4
#define K_ITERS (K_TOTAL / KS)                    // 64
#define NUM_TILES ((M_TOTAL / TILE_M) * (N_TOTAL / TILE_N))   // 1024

#define A_STAGE_BYTES (TILE_M * 128)
#define B_STAGE_BYTES (TILE_N * 128)
#define STAGE_BYTES   (A_STAGE_BYTES + B_STAGE_BYTES)
#define SMEM_TOTAL    (STAGES * STAGE_BYTES)      // 196608

#define FWHT_BLOCKS 4096
#define CONV_BLOCKS 2048

__device__ __align__(1024) __half g_Wh[(size_t)N_TOTAL * K_TOTAL];
__device__ __align__(1024) __half g_Xh[(size_t)M_TOTAL * K_TOTAL];

// ---------------------------------------------------------------------------
__device__ __forceinline__ uint32_t smem_u32(const void* p) {
    uint32_t a;
    asm("{ .reg .u64 t; cvta.to.shared.u64 t, %1; cvt.u32.u64 %0, t; }"
        : "=r"(a) : "l"(p));
    return a;
}
__device__ __forceinline__ void cp_async16(uint32_t dst, const void* src) {
    asm volatile("cp.async.cg.shared.global [%0], [%1], 16;" :: "r"(dst), "l"(src));
}
__device__ __forceinline__ void cp_commit() {
    asm volatile("cp.async.commit_group;" ::: "memory");
}
__device__ __forceinline__ void cp_wait2() {
    asm volatile("cp.async.wait_group 2;" ::: "memory");
}
__device__ __forceinline__ void cp_wait0() {
    asm volatile("cp.async.wait_group 0;" ::: "memory");
}
__device__ __forceinline__ void ldsm_x4(uint32_t* r, uint32_t a) {
    asm volatile("ldmatrix.sync.aligned.m8n8.x4.shared.b16 {%0,%1,%2,%3}, [%4];"
                 : "=r"(r[0]), "=r"(r[1]), "=r"(r[2]), "=r"(r[3]) : "r"(a));
}
__device__ __forceinline__ void mma16816(float* c, const uint32_t* a,
                                         uint32_t b0, uint32_t b1) {
    asm volatile(
        "mma.sync.aligned.m16n8k16.row.col.f32.f16.f16.f32 "
        "{%0,%1,%2,%3}, {%4,%5,%6,%7}, {%8,%9}, {%0,%1,%2,%3};"
        : "+f"(c[0]), "+f"(c[1]), "+f"(c[2]), "+f"(c[3])
        : "r"(a[0]), "r"(a[1]), "r"(a[2]), "r"(a[3]), "r"(b0), "r"(b1));
}
__device__ __forceinline__ uint32_t swz(int row, int cb) {
    return (uint32_t)(row * 128 + (cb ^ ((row & 7) << 4)));
}

// ---------------------------------------------------------------------------
// K1 merged: fwht(W)->fp16  ||  x->fp16
// ---------------------------------------------------------------------------
__device__ __forceinline__ void bfly16(float* r) {
    #pragma unroll
    for (int h = 1; h < 16; h <<= 1)
        #pragma unroll
        for (int i = 0; i < 16; i++)
            if (!(i & h)) {
                float a = r[i], b = r[i + h];
                r[i] = a + b;
                r[i + h] = a - b;
            }
}
__device__ __forceinline__ int fw_phys(int idx) {
    return idx ^ ((idx >> 5) & 15) ^ (((idx >> 8) & 1) << 4);
}

__global__ void __launch_bounds__(256) prep_kernel(const float* __restrict__ W,
                                                   __half* __restrict__ Wh,
                                                   const float4* __restrict__ x,
                                                   __half2* __restrict__ xh) {
    if (blockIdx.x >= FWHT_BLOCKS) {
        const int n4 = (M_TOTAL * K_TOTAL) / 4;
        int i = (blockIdx.x - FWHT_BLOCKS) * blockDim.x + threadIdx.x;
        const int stride = CONV_BLOCKS * blockDim.x;
        for (; i < n4; i += stride) {
            float4 v = x[i];
            xh[2 * i]     = __floats2half2_rn(v.x, v.y);
            xh[2 * i + 1] = __floats2half2_rn(v.z, v.w);
        }
        return;
    }
    __shared__ float s[4096];
    const int t = threadIdx.x;
    const float* src = W + (size_t)blockIdx.x * 4096;
    float r[16];

    #pragma unroll
    for (int j = 0; j < 16; j += 4) {
        float4 v = *(const float4*)(src + t * 16 + j);
        r[j] = v.x; r[j + 1] = v.y; r[j + 2] = v.z; r[j + 3] = v.w;
    }
    bfly16(r);
    #pragma unroll
    for (int j = 0; j < 16; j++) s[fw_phys(t * 16 + j)] = r[j];
    __syncthreads();

    const int hi = t >> 4, lo = t & 15;
    #pragma unroll
    for (int j = 0; j < 16; j++) r[j] = s[fw_phys((hi << 8) | (j << 4) | lo)];
    bfly16(r);
    #pragma unroll
    for (int j = 0; j < 16; j++) s[fw_phys((hi << 8) | (j << 4) | lo)] = r[j];
    __syncthreads();

    #pragma unroll
    for (int j = 0; j < 16; j++) r[j] = s[fw_phys((j << 8) | t)];
    bfly16(r);
    __half* dst = Wh + (size_t)blockIdx.x * 4096;
    #pragma unroll
    for (int j = 0; j < 16; j++)
        dst[(j << 8) | t] = __float2half(r[j] * 0.015625f);
}

// ---------------------------------------------------------------------------
// K2: persistent GEMM  out = Xh * Wh^T + bias
// ---------------------------------------------------------------------------
__global__ void __launch_bounds__(256, 1) gemm_kernel(
    float* __restrict__ out, const float* __restrict__ bias,
    const __half* __restrict__ Xh, const __half* __restrict__ Wh) {
    extern __shared__ char smem[];
    const uint32_t sb = smem_u32(smem);
    const int tid = threadIdx.x;
    const int wid = tid >> 5;
    const int lane = tid & 31;
    const int warp_m = wid >> 1;
    const int warp_n = wid & 1;
    const int stride = gridDim.x;

    auto load_stage = [&](int slot, const char* sA, const char* sBp, int kt) {
        const uint32_t base = sb + slot * STAGE_BYTES;
        const int kb = kt * (KS * 2);
        #pragma unroll
        for (int i = 0; i < 8; i++) {
            int idx = tid + i * 256;
            int row = idx >> 3;
            int cb = (idx & 7) << 4;
            cp_async16(base + swz(row, cb),
                       sA + (size_t)row * (K_TOTAL * 2) + kb + cb);
        }
        #pragma unroll
        for (int i = 0; i < 4; i++) {
            int idx = tid + i * 256;
            int row = idx >> 3;
            int cb = (idx & 7) << 4;
            cp_async16(base + A_STAGE_BYTES + swz(row, cb),
                       sBp + (size_t)row * (K_TOTAL * 2) + kb + cb);
        }
        cp_commit();
    };

    // ldmatrix lane addressing (stage-relative)
    const int a_lrow = warp_m * 64 + (lane & 15);
    const int a_lcb = (lane >> 4) << 4;
    const int g = lane >> 3;
    const int b_lrow = warp_n * 64 + ((g >> 1) << 3) + (lane & 7);
    const int b_lcb = (g & 1) << 4;
    uint32_t offA[4], offB[4];
    #pragma unroll
    for (int mt = 0; mt < 4; mt++) offA[mt] = swz(a_lrow + mt * 16, a_lcb);
    #pragma unroll
    for (int p = 0; p < 4; p++) offB[p] = swz(b_lrow + p * 16, b_lcb);

    uint32_t a[2][4][4], b[2][4][4];
    bool first = true;

    for (int tile = blockIdx.x; tile < NUM_TILES; tile += stride) {
        const int tile_n = tile & 31;
        const int tile_m = tile >> 5;
        const char* curA = (const char*)(Xh + (size_t)tile_m * TILE_M * K_TOTAL);
        const char* curB = (const char*)(Wh + (size_t)tile_n * TILE_N * K_TOTAL);

        const int ntile = tile + stride;
        const bool has_next = ntile < NUM_TILES;
        const char* nxtA = has_next
            ? (const char*)(Xh + (size_t)(ntile >> 5) * TILE_M * K_TOTAL) : curA;
        const char* nxtB = has_next
            ? (const char*)(Wh + (size_t)(ntile & 31) * TILE_N * K_TOTAL) : curB;

        if (first) {                 // one-time prologue; later tiles arrive
            first = false;           // pre-loaded by the previous tile's tail
            load_stage(0, curA, curB, 0);
            load_stage(1, curA, curB, 1);
            load_stage(2, curA, curB, 2);
        }

        float c[4][8][4];
        #pragma unroll
        for (int mt = 0; mt < 4; mt++)
            #pragma unroll
            for (int nt = 0; nt < 8; nt++)
                #pragma unroll
                for (int j = 0; j < 4; j++) c[mt][nt][j] = 0.0f;

        for (int k = 0; k < K_ITERS; k++) {
            // tail of the very last tile: no more commits arrive, so wait2's
            // guarantee degrades -- wait for everything instead.
            if (!has_next && k >= K_ITERS - 2) cp_wait0(); else cp_wait2();
            __syncthreads();

            const uint32_t sA = sb + (k & 3) * STAGE_BYTES;
            const uint32_t sB = sA + A_STAGE_BYTES;

            // prime frag buffer 0 (ks = 0)
            #pragma unroll
            for (int mt = 0; mt < 4; mt++) ldsm_x4(a[0][mt], sA + offA[mt]);
            #pragma unroll
            for (int p = 0; p < 4; p++) ldsm_x4(b[0][p], sB + offB[p]);

            // continuous stage stream: k+3 of this tile, or next tile's head
            {
                const int s = k + 3;
                if (s < K_ITERS)
                    load_stage(s & 3, curA, curB, s);
                else if (has_next)
                    load_stage(s & 3, nxtA, nxtB, s - K_ITERS);
            }

            #pragma unroll
            for (int ks = 0; ks < KS / 16; ks++) {
                const int cur = ks & 1;
                if (ks < KS / 16 - 1) {
                    const int nxt = cur ^ 1;
                    const uint32_t kx = (uint32_t)((ks + 1) << 5);
                    #pragma unroll
                    for (int mt = 0; mt < 4; mt++)
                        ldsm_x4(a[nxt][mt], sA + (offA[mt] ^ kx));
                    #pragma unroll
                    for (int p = 0; p < 4; p++)
                        ldsm_x4(b[nxt][p], sB + (offB[p] ^ kx));
                }
                #pragma unroll
                for (int mt = 0; mt < 4; mt++)
                    #pragma unroll
                    for (int nt = 0; nt < 8; nt++) {
                        const int p = nt >> 1;
                        if (nt & 1)
                            mma16816(c[mt][nt], a[cur][mt], b[cur][p][2], b[cur][p][3]);
                        else
                            mma16816(c[mt][nt], a[cur][mt], b[cur][p][0], b[cur][p][1]);
                    }
            }
        }

        // ---- epilogue (next tile's loads are in flight underneath) ----
        const int n_base = tile_n * TILE_N + warp_n * 64 + (lane & 3) * 2;
        float2 bv[8];
        #pragma unroll
        for (int nt = 0; nt < 8; nt++)
            bv[nt] = *(const float2*)(bias + n_base + nt * 8);

        const int m_base = tile_m * TILE_M + warp_m * 64 + (lane >> 2);
        #pragma unroll
        for (int mt = 0; mt < 4; mt++) {
            const size_t r0 = (size_t)(m_base + mt * 16) * N_TOTAL;
            const size_t r1 = r0 + 8 * N_TOTAL;
            #pragma unroll
            for (int nt = 0; nt < 8; nt++) {
                const int nc = n_base + nt * 8;
                *(float2*)(out + r0 + nc) =
                    make_float2(c[mt][nt][0] + bv[nt].x, c[mt][nt][1] + bv[nt].y);
                *(float2*)(out + r1 + nc) =
                    make_float2(c[mt][nt][2] + bv[nt].x, c[mt][nt][3] + bv[nt].y);
            }
        }
    }
}

// ---------------------------------------------------------------------------
extern "C" void kernel_launch(void* const* d_in, const int* in_sizes, int n_in,
                              void* d_out, int out_size) {
    (void)in_sizes; (void)n_in; (void)out_size;
    const float* x = (const float*)d_in[0];
    const float* W = (const float*)d_in[1];
    const float* b = (const float*)d_in[2];
    float* out = (float*)d_out;

    void *wh_p = nullptr, *xh_p = nullptr;
    cudaGetSymbolAddress(&wh_p, g_Wh);
    cudaGetSymbolAddress(&xh_p, g_Xh);

    static int nsm = 0;
    if (!nsm) {
        cudaDeviceGetAttribute(&nsm, cudaDevAttrMultiProcessorCount, 0);
        if (nsm <= 0) nsm = 148;
        cudaFuncSetAttribute(gemm_kernel,
                             cudaFuncAttributeMaxDynamicSharedMemorySize,
                             SMEM_TOTAL);
    }

    prep_kernel<<<FWHT_BLOCKS + CONV_BLOCKS, 256>>>(
        W, (__half*)wh_p, (const float4*)x, (__half2*)xh_p);

    gemm_kernel<<<nsm, 256, SMEM_TOTAL>>>(
        out, b, (const __half*)xh_p, (const __half*)wh_p);
}

// round 11
// speedup vs baseline: 1.0630x; 1.0630x over previous
#include <cuda_runtime.h>
#include <cuda_fp16.h>
#include <cstdint>

// ============================================================================
// out[8192,4096] = fwht(x) @ W^T + b  ==  x @ fwht(W)^T + b   (H symmetric)
//  K1 (merged): blocks 0..4095    -> Wh = fp16(fwht(W row) / 64)
//               blocks 4096..6143 -> Xh = fp16(x)
//  K2: fp16 HMMA GEMM, 128x128 CTA tile, 4 warps (64x64 warp tile),
//      3-stage cp.async, 2 CTAs/SM (independent barrier domains interleave).
//  (round-10 rerun: A-stage loader fixed to 8 iters = 1024 chunks)
// ============================================================================

#define M_TOTAL 8192
#define N_TOTAL 4096
#define K_TOTAL 4096

#define TILE_M 128
#define TILE_N 128
#define KS 64
#define STAGES 3
#define K_ITERS (K_TOTAL / KS)                    // 64

#define A_STAGE_BYTES (TILE_M * 128)              // 16384
#define B_STAGE_BYTES (TILE_N * 128)              // 16384
#define STAGE_BYTES   (A_STAGE_BYTES + B_STAGE_BYTES)
#define SMEM_TOTAL    (STAGES * STAGE_BYTES)      // 98304 -> 2 CTAs/SM

#define FWHT_BLOCKS 4096
#define CONV_BLOCKS 2048

__device__ __align__(1024) __half g_Wh[(size_t)N_TOTAL * K_TOTAL];
__device__ __align__(1024) __half g_Xh[(size_t)M_TOTAL * K_TOTAL];

// ---------------------------------------------------------------------------
__device__ __forceinline__ uint32_t smem_u32(const void* p) {
    uint32_t a;
    asm("{ .reg .u64 t; cvta.to.shared.u64 t, %1; cvt.u32.u64 %0, t; }"
        : "=r"(a) : "l"(p));
    return a;
}
__device__ __forceinline__ void cp_async16(uint32_t dst, const void* src) {
    asm volatile("cp.async.cg.shared.global [%0], [%1], 16;" :: "r"(dst), "l"(src));
}
__device__ __forceinline__ void cp_commit() {
    asm volatile("cp.async.commit_group;" ::: "memory");
}
__device__ __forceinline__ void cp_wait1() {
    asm volatile("cp.async.wait_group 1;" ::: "memory");
}
__device__ __forceinline__ void cp_wait0() {
    asm volatile("cp.async.wait_group 0;" ::: "memory");
}
__device__ __forceinline__ void ldsm_x4(uint32_t* r, uint32_t a) {
    asm volatile("ldmatrix.sync.aligned.m8n8.x4.shared.b16 {%0,%1,%2,%3}, [%4];"
                 : "=r"(r[0]), "=r"(r[1]), "=r"(r[2]), "=r"(r[3]) : "r"(a));
}
__device__ __forceinline__ void mma16816(float* c, const uint32_t* a,
                                         uint32_t b0, uint32_t b1) {
    asm volatile(
        "mma.sync.aligned.m16n8k16.row.col.f32.f16.f16.f32 "
        "{%0,%1,%2,%3}, {%4,%5,%6,%7}, {%8,%9}, {%0,%1,%2,%3};"
        : "+f"(c[0]), "+f"(c[1]), "+f"(c[2]), "+f"(c[3])
        : "r"(a[0]), "r"(a[1]), "r"(a[2]), "r"(a[3]), "r"(b0), "r"(b1));
}
__device__ __forceinline__ uint32_t swz(int row, int cb) {
    return (uint32_t)(row * 128 + (cb ^ ((row & 7) << 4)));
}

// ---------------------------------------------------------------------------
// K1 merged: fwht(W)->fp16  ||  x->fp16
// ---------------------------------------------------------------------------
__device__ __forceinline__ void bfly16(float* r) {
    #pragma unroll
    for (int h = 1; h < 16; h <<= 1)
        #pragma unroll
        for (int i = 0; i < 16; i++)
            if (!(i & h)) {
                float a = r[i], b = r[i + h];
                r[i] = a + b;
                r[i + h] = a - b;
            }
}
__device__ __forceinline__ int fw_phys(int idx) {
    return idx ^ ((idx >> 5) & 15) ^ (((idx >> 8) & 1) << 4);
}

__global__ void __launch_bounds__(256) prep_kernel(const float* __restrict__ W,
                                                   __half* __restrict__ Wh,
                                                   const float4* __restrict__ x,
                                                   __half2* __restrict__ xh) {
    if (blockIdx.x >= FWHT_BLOCKS) {
        const int n4 = (M_TOTAL * K_TOTAL) / 4;
        int i = (blockIdx.x - FWHT_BLOCKS) * blockDim.x + threadIdx.x;
        const int stride = CONV_BLOCKS * blockDim.x;
        for (; i < n4; i += stride) {
            float4 v = x[i];
            xh[2 * i]     = __floats2half2_rn(v.x, v.y);
            xh[2 * i + 1] = __floats2half2_rn(v.z, v.w);
        }
        return;
    }
    __shared__ float s[4096];
    const int t = threadIdx.x;
    const float* src = W + (size_t)blockIdx.x * 4096;
    float r[16];

    #pragma unroll
    for (int j = 0; j < 16; j += 4) {
        float4 v = *(const float4*)(src + t * 16 + j);
        r[j] = v.x; r[j + 1] = v.y; r[j + 2] = v.z; r[j + 3] = v.w;
    }
    bfly16(r);
    #pragma unroll
    for (int j = 0; j < 16; j++) s[fw_phys(t * 16 + j)] = r[j];
    __syncthreads();

    const int hi = t >> 4, lo = t & 15;
    #pragma unroll
    for (int j = 0; j < 16; j++) r[j] = s[fw_phys((hi << 8) | (j << 4) | lo)];
    bfly16(r);
    #pragma unroll
    for (int j = 0; j < 16; j++) s[fw_phys((hi << 8) | (j << 4) | lo)] = r[j];
    __syncthreads();

    #pragma unroll
    for (int j = 0; j < 16; j++) r[j] = s[fw_phys((j << 8) | t)];
    bfly16(r);
    __half* dst = Wh + (size_t)blockIdx.x * 4096;
    #pragma unroll
    for (int j = 0; j < 16; j++)
        dst[(j << 8) | t] = __float2half(r[j] * 0.015625f);
}

// ---------------------------------------------------------------------------
// K2: GEMM  out = Xh[8192,4096] * Wh[4096,4096]^T + bias
//     CTA 128x128, 4 warps (2x2), warp tile 64x64, 2 CTAs/SM
// ---------------------------------------------------------------------------
__global__ void __launch_bounds__(128, 2) gemm_kernel(
    float* __restrict__ out, const float* __restrict__ bias,
    const __half* __restrict__ Xh, const __half* __restrict__ Wh) {
    extern __shared__ char smem[];
    const uint32_t sb = smem_u32(smem);
    const int tid = threadIdx.x;
    const int wid = tid >> 5;
    const int lane = tid & 31;

    const int tile_n = blockIdx.x & 31;           // N/128 = 32
    const int tile_m = blockIdx.x >> 5;           // M/128 = 64
    const int warp_m = wid >> 1;                  // 0..1
    const int warp_n = wid & 1;                   // 0..1

    const char* srcA = (const char*)(Xh + (size_t)tile_m * TILE_M * K_TOTAL);
    const char* srcB = (const char*)(Wh + (size_t)tile_n * TILE_N * K_TOTAL);

    auto load_stage = [&](int slot, int kt) {
        const uint32_t base = sb + slot * STAGE_BYTES;
        const int kb = kt * (KS * 2);
        #pragma unroll
        for (int i = 0; i < 8; i++) {             // A: 128 rows -> 1024 chunks
            int idx = tid + i * 128;
            int row = idx >> 3;
            int cb = (idx & 7) << 4;
            cp_async16(base + swz(row, cb),
                       srcA + (size_t)row * (K_TOTAL * 2) + kb + cb);
        }
        #pragma unroll
        for (int i = 0; i < 8; i++) {             // B: 128 rows -> 1024 chunks
            int idx = tid + i * 128;
            int row = idx >> 3;
            int cb = (idx & 7) << 4;
            cp_async16(base + A_STAGE_BYTES + swz(row, cb),
                       srcB + (size_t)row * (K_TOTAL * 2) + kb + cb);
        }
        cp_commit();
    };

    float c[4][8][4];
    #pragma unroll
    for (int mt = 0; mt < 4; mt++)
        #pragma unroll
        for (int nt = 0; nt < 8; nt++)
            #pragma unroll
            for (int j = 0; j < 4; j++) c[mt][nt][j] = 0.0f;

    load_stage(0, 0);
    load_stage(1, 1);

    const int a_lrow = warp_m * 64 + (lane & 15);
    const int a_lcb = (lane >> 4) << 4;
    const int g = lane >> 3;
    const int b_lrow = warp_n * 64 + ((g >> 1) << 3) + (lane & 7);
    const int b_lcb = (g & 1) << 4;
    uint32_t offA[4], offB[4];
    #pragma unroll
    for (int mt = 0; mt < 4; mt++) offA[mt] = swz(a_lrow + mt * 16, a_lcb);
    #pragma unroll
    for (int p = 0; p < 4; p++) offB[p] = swz(b_lrow + p * 16, b_lcb);

    uint32_t a[2][4][4], b[2][4][4];

    int rd = 0, wr = 2;
    for (int k = 0; k < K_ITERS; k++) {
        if (k == K_ITERS - 1) cp_wait0(); else cp_wait1();
        __syncthreads();

        const uint32_t sA = sb + rd * STAGE_BYTES;
        const uint32_t sB = sA + A_STAGE_BYTES;

        // prime frag buffer 0 (ks = 0)
        #pragma unroll
        for (int mt = 0; mt < 4; mt++) ldsm_x4(a[0][mt], sA + offA[mt]);
        #pragma unroll
        for (int p = 0; p < 4; p++) ldsm_x4(b[0][p], sB + offB[p]);

        if (k + 2 < K_ITERS) load_stage(wr, k + 2);

        #pragma unroll
        for (int ks = 0; ks < KS / 16; ks++) {
            const int cur = ks & 1;
            if (ks < KS / 16 - 1) {
                const int nxt = cur ^ 1;
                const uint32_t kx = (uint32_t)((ks + 1) << 5);
                #pragma unroll
                for (int mt = 0; mt < 4; mt++)
                    ldsm_x4(a[nxt][mt], sA + (offA[mt] ^ kx));
                #pragma unroll
                for (int p = 0; p < 4; p++)
                    ldsm_x4(b[nxt][p], sB + (offB[p] ^ kx));
            }
            #pragma unroll
            for (int mt = 0; mt < 4; mt++)
                #pragma unroll
                for (int nt = 0; nt < 8; nt++) {
                    const int p = nt >> 1;
                    if (nt & 1)
                        mma16816(c[mt][nt], a[cur][mt], b[cur][p][2], b[cur][p][3]);
                    else
                        mma16816(c[mt][nt], a[cur][mt], b[cur][p][0], b[cur][p][1]);
                }
        }
        rd = (rd == STAGES - 1) ? 0 : rd + 1;
        wr = (wr == STAGES - 1) ? 0 : wr + 1;
    }

    // ---- epilogue: fused bias, float2 stores ----
    const int n_base = tile_n * TILE_N + warp_n * 64 + (lane & 3) * 2;
    float2 bv[8];
    #pragma unroll
    for (int nt = 0; nt < 8; nt++)
        bv[nt] = *(const float2*)(bias + n_base + nt * 8);

    const int m_base = tile_m * TILE_M + warp_m * 64 + (lane >> 2);
    #pragma unroll
    for (int mt = 0; mt < 4; mt++) {
        const size_t r0 = (size_t)(m_base + mt * 16) * N_TOTAL;
        const size_t r1 = r0 + 8 * N_TOTAL;
        #pragma unroll
        for (int nt = 0; nt < 8; nt++) {
            const int nc = n_base + nt * 8;
            *(float2*)(out + r0 + nc) =
                make_float2(c[mt][nt][0] + bv[nt].x, c[mt][nt][1] + bv[nt].y);
            *(float2*)(out + r1 + nc) =
                make_float2(c[mt][nt][2] + bv[nt].x, c[mt][nt][3] + bv[nt].y);
        }
    }
}

// ---------------------------------------------------------------------------
extern "C" void kernel_launch(void* const* d_in, const int* in_sizes, int n_in,
                              void* d_out, int out_size) {
    (void)in_sizes; (void)n_in; (void)out_size;
    const float* x = (const float*)d_in[0];
    const float* W = (const float*)d_in[1];
    const float* b = (const float*)d_in[2];
    float* out = (float*)d_out;

    void *wh_p = nullptr, *xh_p = nullptr;
    cudaGetSymbolAddress(&wh_p, g_Wh);
    cudaGetSymbolAddress(&xh_p, g_Xh);

    static bool cfg = false;
    if (!cfg) {
        cudaFuncSetAttribute(gemm_kernel,
                             cudaFuncAttributeMaxDynamicSharedMemorySize,
                             SMEM_TOTAL);
        cfg = true;
    }

    prep_kernel<<<FWHT_BLOCKS + CONV_BLOCKS, 256>>>(
        W, (__half*)wh_p, (const float4*)x, (__half2*)xh_p);

    gemm_kernel<<<(M_TOTAL / TILE_M) * (N_TOTAL / TILE_N), 128, SMEM_TOTAL>>>(
        out, b, (const __half*)xh_p, (const __half*)wh_p);
}

// round 13
// speedup vs baseline: 1.1194x; 1.0531x over previous
#include <cuda_runtime.h>
#include <cuda_fp16.h>
#include <cstdint>

// ============================================================================
// out[8192,4096] = fwht(x) @ W^T + b  ==  x @ fwht(W)^T + b   (H symmetric)
//  K1 (merged): blocks 0..4095    -> Wh = fp16(fwht(W row) / 64)
//               blocks 4096..6143 -> Xh = fp16(x)
//  K2: fp16 HMMA GEMM, 128x128 CTA tile, 4 warps (64x64 warp tile),
//      3-stage cp.async, 2 CTAs/SM.  (round-11 structure; the next-stage
//      cp.async burst is issued at ks==2 instead of the iteration head so it
//      doesn't collide with the post-barrier fragment-prime LDSMs.)
// ============================================================================

#define M_TOTAL 8192
#define N_TOTAL 4096
#define K_TOTAL 4096

#define TILE_M 128
#define TILE_N 128
#define KS 64
#define STAGES 3
#define K_ITERS (K_TOTAL / KS)                    // 64

#define A_STAGE_BYTES (TILE_M * 128)              // 16384
#define B_STAGE_BYTES (TILE_N * 128)              // 16384
#define STAGE_BYTES   (A_STAGE_BYTES + B_STAGE_BYTES)
#define SMEM_TOTAL    (STAGES * STAGE_BYTES)      // 98304 -> 2 CTAs/SM

#define FWHT_BLOCKS 4096
#define CONV_BLOCKS 2048

__device__ __align__(1024) __half g_Wh[(size_t)N_TOTAL * K_TOTAL];
__device__ __align__(1024) __half g_Xh[(size_t)M_TOTAL * K_TOTAL];

// ---------------------------------------------------------------------------
__device__ __forceinline__ uint32_t smem_u32(const void* p) {
    uint32_t a;
    asm("{ .reg .u64 t; cvta.to.shared.u64 t, %1; cvt.u32.u64 %0, t; }"
        : "=r"(a) : "l"(p));
    return a;
}
__device__ __forceinline__ void cp_async16(uint32_t dst, const void* src) {
    asm volatile("cp.async.cg.shared.global [%0], [%1], 16;" :: "r"(dst), "l"(src));
}
__device__ __forceinline__ void cp_commit() {
    asm volatile("cp.async.commit_group;" ::: "memory");
}
__device__ __forceinline__ void cp_wait1() {
    asm volatile("cp.async.wait_group 1;" ::: "memory");
}
__device__ __forceinline__ void cp_wait0() {
    asm volatile("cp.async.wait_group 0;" ::: "memory");
}
__device__ __forceinline__ void ldsm_x4(uint32_t* r, uint32_t a) {
    asm volatile("ldmatrix.sync.aligned.m8n8.x4.shared.b16 {%0,%1,%2,%3}, [%4];"
                 : "=r"(r[0]), "=r"(r[1]), "=r"(r[2]), "=r"(r[3]) : "r"(a));
}
__device__ __forceinline__ void mma16816(float* c, const uint32_t* a,
                                         uint32_t b0, uint32_t b1) {
    asm volatile(
        "mma.sync.aligned.m16n8k16.row.col.f32.f16.f16.f32 "
        "{%0,%1,%2,%3}, {%4,%5,%6,%7}, {%8,%9}, {%0,%1,%2,%3};"
        : "+f"(c[0]), "+f"(c[1]), "+f"(c[2]), "+f"(c[3])
        : "r"(a[0]), "r"(a[1]), "r"(a[2]), "r"(a[3]), "r"(b0), "r"(b1));
}
__device__ __forceinline__ uint32_t swz(int row, int cb) {
    return (uint32_t)(row * 128 + (cb ^ ((row & 7) << 4)));
}

// ---------------------------------------------------------------------------
// K1 merged: fwht(W)->fp16  ||  x->fp16
// ---------------------------------------------------------------------------
__device__ __forceinline__ void bfly16(float* r) {
    #pragma unroll
    for (int h = 1; h < 16; h <<= 1)
        #pragma unroll
        for (int i = 0; i < 16; i++)
            if (!(i & h)) {
                float a = r[i], b = r[i + h];
                r[i] = a + b;
                r[i + h] = a - b;
            }
}
__device__ __forceinline__ int fw_phys(int idx) {
    return idx ^ ((idx >> 5) & 15) ^ (((idx >> 8) & 1) << 4);
}

__global__ void __launch_bounds__(256) prep_kernel(const float* __restrict__ W,
                                                   __half* __restrict__ Wh,
                                                   const float4* __restrict__ x,
                                                   __half2* __restrict__ xh) {
    if (blockIdx.x >= FWHT_BLOCKS) {
        const int n4 = (M_TOTAL * K_TOTAL) / 4;
        int i = (blockIdx.x - FWHT_BLOCKS) * blockDim.x + threadIdx.x;
        const int stride = CONV_BLOCKS * blockDim.x;
        for (; i < n4; i += stride) {
            float4 v = x[i];
            xh[2 * i]     = __floats2half2_rn(v.x, v.y);
            xh[2 * i + 1] = __floats2half2_rn(v.z, v.w);
        }
        return;
    }
    __shared__ float s[4096];
    const int t = threadIdx.x;
    const float* src = W + (size_t)blockIdx.x * 4096;
    float r[16];

    #pragma unroll
    for (int j = 0; j < 16; j += 4) {
        float4 v = *(const float4*)(src + t * 16 + j);
        r[j] = v.x; r[j + 1] = v.y; r[j + 2] = v.z; r[j + 3] = v.w;
    }
    bfly16(r);
    #pragma unroll
    for (int j = 0; j < 16; j++) s[fw_phys(t * 16 + j)] = r[j];
    __syncthreads();

    const int hi = t >> 4, lo = t & 15;
    #pragma unroll
    for (int j = 0; j < 16; j++) r[j] = s[fw_phys((hi << 8) | (j << 4) | lo)];
    bfly16(r);
    #pragma unroll
    for (int j = 0; j < 16; j++) s[fw_phys((hi << 8) | (j << 4) | lo)] = r[j];
    __syncthreads();

    #pragma unroll
    for (int j = 0; j < 16; j++) r[j] = s[fw_phys((j << 8) | t)];
    bfly16(r);
    __half* dst = Wh + (size_t)blockIdx.x * 4096;
    #pragma unroll
    for (int j = 0; j < 16; j++)
        dst[(j << 8) | t] = __float2half(r[j] * 0.015625f);
}

// ---------------------------------------------------------------------------
// K2: GEMM  out = Xh[8192,4096] * Wh[4096,4096]^T + bias
//     CTA 128x128, 4 warps (2x2), warp tile 64x64, 2 CTAs/SM
// ---------------------------------------------------------------------------
__global__ void __launch_bounds__(128, 2) gemm_kernel(
    float* __restrict__ out, const float* __restrict__ bias,
    const __half* __restrict__ Xh, const __half* __restrict__ Wh) {
    extern __shared__ char smem[];
    const uint32_t sb = smem_u32(smem);
    const int tid = threadIdx.x;
    const int wid = tid >> 5;
    const int lane = tid & 31;

    const int tile_n = blockIdx.x & 31;           // N/128 = 32
    const int tile_m = blockIdx.x >> 5;           // M/128 = 64
    const int warp_m = wid >> 1;                  // 0..1
    const int warp_n = wid & 1;                   // 0..1

    const char* srcA = (const char*)(Xh + (size_t)tile_m * TILE_M * K_TOTAL);
    const char* srcB = (const char*)(Wh + (size_t)tile_n * TILE_N * K_TOTAL);

    auto load_stage = [&](int slot, int kt) {
        const uint32_t base = sb + slot * STAGE_BYTES;
        const int kb = kt * (KS * 2);
        #pragma unroll
        for (int i = 0; i < 8; i++) {             // A: 128 rows -> 1024 chunks
            int idx = tid + i * 128;
            int row = idx >> 3;
            int cb = (idx & 7) << 4;
            cp_async16(base + swz(row, cb),
                       srcA + (size_t)row * (K_TOTAL * 2) + kb + cb);
        }
        #pragma unroll
        for (int i = 0; i < 8; i++) {             // B: 128 rows -> 1024 chunks
            int idx = tid + i * 128;
            int row = idx >> 3;
            int cb = (idx & 7) << 4;
            cp_async16(base + A_STAGE_BYTES + swz(row, cb),
                       srcB + (size_t)row * (K_TOTAL * 2) + kb + cb);
        }
        cp_commit();
    };

    float c[4][8][4];
    #pragma unroll
    for (int mt = 0; mt < 4; mt++)
        #pragma unroll
        for (int nt = 0; nt < 8; nt++)
            #pragma unroll
            for (int j = 0; j < 4; j++) c[mt][nt][j] = 0.0f;

    load_stage(0, 0);
    load_stage(1, 1);

    const int a_lrow = warp_m * 64 + (lane & 15);
    const int a_lcb = (lane >> 4) << 4;
    const int g = lane >> 3;
    const int b_lrow = warp_n * 64 + ((g >> 1) << 3) + (lane & 7);
    const int b_lcb = (g & 1) << 4;
    uint32_t offA[4], offB[4];
    #pragma unroll
    for (int mt = 0; mt < 4; mt++) offA[mt] = swz(a_lrow + mt * 16, a_lcb);
    #pragma unroll
    for (int p = 0; p < 4; p++) offB[p] = swz(b_lrow + p * 16, b_lcb);

    uint32_t a[2][4][4], b[2][4][4];

    int rd = 0, wr = 2;
    for (int k = 0; k < K_ITERS; k++) {
        if (k == K_ITERS - 1) cp_wait0(); else cp_wait1();
        __syncthreads();

        const uint32_t sA = sb + rd * STAGE_BYTES;
        const uint32_t sB = sA + A_STAGE_BYTES;

        // prime frag buffer 0 (ks = 0) -- LSU queue is empty here
        #pragma unroll
        for (int mt = 0; mt < 4; mt++) ldsm_x4(a[0][mt], sA + offA[mt]);
        #pragma unroll
        for (int p = 0; p < 4; p++) ldsm_x4(b[0][p], sB + offB[p]);

        #pragma unroll
        for (int ks = 0; ks < KS / 16; ks++) {
            const int cur = ks & 1;
            if (ks < KS / 16 - 1) {
                const int nxt = cur ^ 1;
                const uint32_t kx = (uint32_t)((ks + 1) << 5);
                #pragma unroll
                for (int mt = 0; mt < 4; mt++)
                    ldsm_x4(a[nxt][mt], sA + (offA[mt] ^ kx));
                #pragma unroll
                for (int p = 0; p < 4; p++)
                    ldsm_x4(b[nxt][p], sB + (offB[p] ^ kx));
            }
            // issue the next stage mid-loop: after the ks=0..2 LDSMs have
            // cleared the LSU, before the register-heavy ks=3..7 stretch.
            // Pure reordering within iter k (same single commit per iter,
            // still >= 2 full iterations ahead of its wait) -> semantics of
            // the wait1 pipeline are unchanged.
            if (ks == 2 && k + 2 < K_ITERS) load_stage(wr, k + 2);

            #pragma unroll
            for (int mt = 0; mt < 4; mt++)
                #pragma unroll
                for (int nt = 0; nt < 8; nt++) {
                    const int p = nt >> 1;
                    if (nt & 1)
                        mma16816(c[mt][nt], a[cur][mt], b[cur][p][2], b[cur][p][3]);
                    else
                        mma16816(c[mt][nt], a[cur][mt], b[cur][p][0], b[cur][p][1]);
                }
        }
        rd = (rd == STAGES - 1) ? 0 : rd + 1;
        wr = (wr == STAGES - 1) ? 0 : wr + 1;
    }

    // ---- epilogue: fused bias, float2 stores ----
    const int n_base = tile_n * TILE_N + warp_n * 64 + (lane & 3) * 2;
    float2 bv[8];
    #pragma unroll
    for (int nt = 0; nt < 8; nt++)
        bv[nt] = *(const float2*)(bias + n_base + nt * 8);

    const int m_base = tile_m * TILE_M + warp_m * 64 + (lane >> 2);
    #pragma unroll
    for (int mt = 0; mt < 4; mt++) {
        const size_t r0 = (size_t)(m_base + mt * 16) * N_TOTAL;
        const size_t r1 = r0 + 8 * N_TOTAL;
        #pragma unroll
        for (int nt = 0; nt < 8; nt++) {
            const int nc = n_base + nt * 8;
            *(float2*)(out + r0 + nc) =
                make_float2(c[mt][nt][0] + bv[nt].x, c[mt][nt][1] + bv[nt].y);
            *(float2*)(out + r1 + nc) =
                make_float2(c[mt][nt][2] + bv[nt].x, c[mt][nt][3] + bv[nt].y);
        }
    }
}

// ---------------------------------------------------------------------------
extern "C" void kernel_launch(void* const* d_in, const int* in_sizes, int n_in,
                              void* d_out, int out_size) {
    (void)in_sizes; (void)n_in; (void)out_size;
    const float* x = (const float*)d_in[0];
    const float* W = (const float*)d_in[1];
    const float* b = (const float*)d_in[2];
    float* out = (float*)d_out;

    void *wh_p = nullptr, *xh_p = nullptr;
    cudaGetSymbolAddress(&wh_p, g_Wh);
    cudaGetSymbolAddress(&xh_p, g_Xh);

    static bool cfg = false;
    if (!cfg) {
        cudaFuncSetAttribute(gemm_kernel,
                             cudaFuncAttributeMaxDynamicSharedMemorySize,
                             SMEM_TOTAL);
        cfg = true;
    }

    prep_kernel<<<FWHT_BLOCKS + CONV_BLOCKS, 256>>>(
        W, (__half*)wh_p, (const float4*)x, (__half2*)xh_p);

    gemm_kernel<<<(M_TOTAL / TILE_M) * (N_TOTAL / TILE_N), 128, SMEM_TOTAL>>>(
        out, b, (const __half*)xh_p, (const __half*)wh_p);
}